// round 15
// baseline (speedup 1.0000x reference)
#include <cuda_runtime.h>
#include <cuda_fp16.h>
#include <math.h>
#include <stdint.h>

#define Bn 2
#define Ln 2048
#define Dn 2048
#define Hn 16
#define DHn 128
#define MROWS (Bn*Ln)          // 4096
#define NQKV  (3*Dn)           // 6144
#define MAXPOS 4096

// ---------------- scratch (device globals; no allocation allowed) ----------
__device__ __half g_xH[(size_t)MROWS*Dn];
__device__ __half g_wH[4][(size_t)Dn*Dn];      // Wq,Wk,Wv contiguous; Wo last
__device__ __half g_QKVf[(size_t)MROWS*NQKV];  // fused Q|K|V fp16, post-RoPE (Q pre-scaled)
__device__ __half g_OH[(size_t)MROWS*Dn];
__device__ float g_cos[MAXPOS*64];
__device__ float g_sin[MAXPOS*64];

// ======================= helpers ============================================
__device__ __forceinline__ uint32_t smem_u32(const void* p){
    uint32_t a;
    asm("{ .reg .u64 t; cvta.to.shared.u64 t, %1; cvt.u32.u64 %0, t; }" : "=r"(a) : "l"(p));
    return a;
}
__device__ __forceinline__ void cp16(uint32_t s, const void* g){
    asm volatile("cp.async.cg.shared.global [%0], [%1], 16;" :: "r"(s), "l"(g));
}
__device__ __forceinline__ void ldsm4(uint32_t* r, uint32_t a){
    asm volatile("ldmatrix.sync.aligned.m8n8.x4.shared.b16 {%0,%1,%2,%3},[%4];"
        : "=r"(r[0]),"=r"(r[1]),"=r"(r[2]),"=r"(r[3]) : "r"(a));
}
__device__ __forceinline__ void ldsm4t(uint32_t* r, uint32_t a){
    asm volatile("ldmatrix.sync.aligned.m8n8.x4.trans.shared.b16 {%0,%1,%2,%3},[%4];"
        : "=r"(r[0]),"=r"(r[1]),"=r"(r[2]),"=r"(r[3]) : "r"(a));
}
__device__ __forceinline__ void mma_f16(float* c, const uint32_t* a, uint32_t b0, uint32_t b1){
    asm volatile("mma.sync.aligned.m16n8k16.row.col.f32.f16.f16.f32 "
        "{%0,%1,%2,%3},{%4,%5,%6,%7},{%8,%9},{%0,%1,%2,%3};"
        : "+f"(c[0]),"+f"(c[1]),"+f"(c[2]),"+f"(c[3])
        : "r"(a[0]),"r"(a[1]),"r"(a[2]),"r"(a[3]),"r"(b0),"r"(b1));
}
__device__ __forceinline__ uint32_t packh2(float x, float y){
    __half2 h = __floats2half2_rn(x, y);
    return *(uint32_t*)&h;
}
__device__ __forceinline__ float ex2(float x){
    float r;
    asm("ex2.approx.f32 %0, %1;" : "=f"(r) : "f"(x));
    return r;
}

// ======================= conversion + RoPE tables (1 launch) ================
__global__ void conv_all(const float* __restrict__ x,
                         const float* __restrict__ Wq, const float* __restrict__ Wk,
                         const float* __restrict__ Wv, const float* __restrict__ Wo)
{
    const int n4w = Dn*Dn/4;
    int y = blockIdx.y;
    if (y == 6){
        int idx = blockIdx.x*blockDim.x + threadIdx.x;
        if (idx >= MAXPOS*64) return;
        int pos = idx >> 6;
        int i   = idx & 63;
        float expo = (float)(2*i) * (1.0f/128.0f);
        float inv  = 1.0f / powf(10000.0f, expo);
        float ang  = (float)pos * inv;
        g_cos[idx] = cosf(ang);
        g_sin[idx] = sinf(ang);
        return;
    }
    const float* src;
    __half* dst;
    if (y < 4){
        src = (y==0)?Wq:((y==1)?Wk:((y==2)?Wv:Wo));
        dst = &g_wH[y][0];
    } else {
        src = x  + (size_t)(y-4)*n4w*4;
        dst = g_xH + (size_t)(y-4)*n4w*4;
    }
    int i = blockIdx.x*blockDim.x + threadIdx.x;
    if (i >= n4w) return;
    float4 v = ((const float4*)src)[i];
    ((uint2*)dst)[i] = make_uint2(packh2(v.x,v.y), packh2(v.z,v.w));
}

// ======================= fused QKV GEMM + RoPE epilogue =====================
// Tile 128x192, 8 warps (2x4), warp tile 64x48, BK=64, 3-stage, OCC=1.
// Row pitch 144 B. 32 k-iterations (half the barrier count of BK=32).
#define QAW     18432                 // A bytes per stage (128 x 144)
#define QSTAGE  46080                 // + W 192 x 144
#define QG_SMEM (3*QSTAGE)            // 138240

__global__ __launch_bounds__(256)
void gemm_qkv(const __half* __restrict__ A, const __half* __restrict__ W,
              const int* __restrict__ tp, __half* __restrict__ Cf)
{
    extern __shared__ char smem[];
    uint32_t sb = smem_u32(smem);
    const int tid = threadIdx.x, wid = tid>>5, lane = tid&31;
    const int m0 = blockIdx.y*128, n0 = blockIdx.x*192;
    const int warp_m = (wid>>2)*64, warp_n = (wid&3)*48;

    auto load_stage = [&](int st, int kt){
        uint32_t sbase = sb + st*QSTAGE;
        #pragma unroll
        for (int j=0;j<10;j++){
            int c = tid + j*256;
            if (c < 1024){
                int row = c>>3, seg = c&7;
                cp16(sbase + row*144 + seg*16,
                     A + (size_t)(m0+row)*Dn + kt*64 + seg*8);
            } else {
                int cc = c - 1024; int row = cc>>3, seg = cc&7;
                cp16(sbase + QAW + row*144 + seg*16,
                     W + (size_t)(n0+row)*Dn + kt*64 + seg*8);
            }
        }
    };

    float acc[4][6][4];
    #pragma unroll
    for (int i=0;i<4;i++)
        #pragma unroll
        for (int j=0;j<6;j++)
            #pragma unroll
            for (int q=0;q<4;q++) acc[i][j][q]=0.f;

    load_stage(0, 0);
    asm volatile("cp.async.commit_group;");
    load_stage(1, 1);
    asm volatile("cp.async.commit_group;");

    const int lrow = lane & 15;
    const uint32_t lcolB = (uint32_t)((lane>>4)<<4);

    for (int kt=0; kt<32; ++kt){
        int st = kt - (kt/3)*3;
        uint32_t base = sb + st*QSTAGE;
        asm volatile("cp.async.wait_group 1;");
        __syncthreads();

        #pragma unroll
        for (int ks=0; ks<4; ++ks){
            uint32_t kB = ks*32;
            uint32_t aAddr = base + (uint32_t)(warp_m + lrow)*144 + lcolB + kB;
            uint32_t wAddr = base + QAW + (uint32_t)(warp_n + lrow)*144 + lcolB + kB;

            uint32_t ahr[4][4], whr[3][4];
            #pragma unroll
            for (int mt=0; mt<4; mt++) ldsm4(ahr[mt], aAddr + mt*(16*144));
            #pragma unroll
            for (int p=0; p<3; p++)   ldsm4(whr[p], wAddr + p*(16*144));
            #pragma unroll
            for (int mt=0; mt<4; mt++)
                #pragma unroll
                for (int p=0; p<3; p++){
                    mma_f16(acc[mt][2*p],   ahr[mt], whr[p][0], whr[p][2]);
                    mma_f16(acc[mt][2*p+1], ahr[mt], whr[p][1], whr[p][3]);
                }
        }

        if (kt+2 < 32){
            int st2 = (kt+2) - ((kt+2)/3)*3;
            load_stage(st2, kt+2);
        }
        asm volatile("cp.async.commit_group;");
        __syncthreads();
    }

    // ---- epilogue: RoPE (Q: * scale2, K: plain) + fp16 store ----
    const float scale2 = 0.12753785166876984f;   // 1/sqrt(128)*log2(e)
    const int row0 = m0 + warp_m + (lane>>2);
    const int col0 = n0 + warp_n + ((lane&3)<<1);
    int pos[8];
    #pragma unroll
    for (int mt=0; mt<4; mt++){
        pos[2*mt]   = tp[row0 + mt*16];
        pos[2*mt+1] = tp[row0 + mt*16 + 8];
    }
    #pragma unroll
    for (int nt=0; nt<6; nt++){
        int col = col0 + nt*8;
        bool dorope = (col < 2*Dn);
        float qs = (col < Dn) ? scale2 : 1.0f;
        int ii = (col & 127) >> 1;
        #pragma unroll
        for (int mt=0; mt<4; mt++){
            float a0=acc[mt][nt][0], a1=acc[mt][nt][1];
            float a2=acc[mt][nt][2], a3=acc[mt][nt][3];
            uint32_t o0, o1;
            if (dorope){
                int p0 = pos[2*mt]*64 + ii, p1 = pos[2*mt+1]*64 + ii;
                float c0=g_cos[p0]*qs, s0=g_sin[p0]*qs;
                float c1=g_cos[p1]*qs, s1=g_sin[p1]*qs;
                o0 = packh2(a0*c0 - a1*s0, a0*s0 + a1*c0);
                o1 = packh2(a2*c1 - a3*s1, a2*s1 + a3*c1);
            } else {
                o0 = packh2(a0, a1);
                o1 = packh2(a2, a3);
            }
            *(uint32_t*)&Cf[(size_t)(row0 + mt*16)*NQKV + col]     = o0;
            *(uint32_t*)&Cf[(size_t)(row0 + mt*16 + 8)*NQKV + col] = o1;
        }
    }
}

// ======================= fp16 GEMM (output projection) ======================
// 128x128 tile, warp 64x32, BK=64, 3-stage, OCC=2.  (R12/R13 measured win)
#define FAW     18432
#define FSTAGE  36864
#define FG_SMEM (3*FSTAGE)            // 110592

__global__ __launch_bounds__(256, 2)
void gemm_fp16(const __half* __restrict__ A, const __half* __restrict__ W,
               float* __restrict__ C)
{
    extern __shared__ char smem[];
    uint32_t sb = smem_u32(smem);
    const int tid = threadIdx.x, wid = tid>>5, lane = tid&31;
    const int m0 = blockIdx.y*128, n0 = blockIdx.x*128;
    const int warp_m = (wid>>2)*64, warp_n = (wid&3)*32;

    auto load_stage = [&](int st, int kt){
        uint32_t sbase = sb + st*FSTAGE;
        #pragma unroll
        for (int j=0;j<8;j++){
            int c = tid + j*256;
            if (c < 1024){
                int row = c>>3, seg = c&7;
                cp16(sbase + row*144 + seg*16,
                     A + (size_t)(m0+row)*Dn + kt*64 + seg*8);
            } else {
                int cc = c - 1024; int row = cc>>3, seg = cc&7;
                cp16(sbase + FAW + row*144 + seg*16,
                     W + (size_t)(n0+row)*Dn + kt*64 + seg*8);
            }
        }
    };

    float acc[4][4][4];
    #pragma unroll
    for (int i=0;i<4;i++)
        #pragma unroll
        for (int j=0;j<4;j++)
            #pragma unroll
            for (int q=0;q<4;q++) acc[i][j][q]=0.f;

    load_stage(0, 0);
    asm volatile("cp.async.commit_group;");
    load_stage(1, 1);
    asm volatile("cp.async.commit_group;");

    const int lrow = lane & 15;
    const uint32_t lcolB = (uint32_t)((lane>>4)<<4);

    for (int kt=0; kt<32; ++kt){
        int st = kt - (kt/3)*3;
        uint32_t base = sb + st*FSTAGE;
        asm volatile("cp.async.wait_group 1;");
        __syncthreads();

        #pragma unroll
        for (int ks=0; ks<4; ++ks){
            uint32_t kB = ks*32;
            uint32_t aAddr = base + (uint32_t)(warp_m + lrow)*144 + lcolB + kB;
            uint32_t wAddr = base + FAW + (uint32_t)(warp_n + lrow)*144 + lcolB + kB;

            uint32_t ahr[4][4], whr[2][4];
            #pragma unroll
            for (int mt=0; mt<4; mt++) ldsm4(ahr[mt], aAddr + mt*(16*144));
            #pragma unroll
            for (int p=0; p<2; p++)   ldsm4(whr[p], wAddr + p*(16*144));
            #pragma unroll
            for (int mt=0; mt<4; mt++)
                #pragma unroll
                for (int p=0; p<2; p++){
                    mma_f16(acc[mt][2*p],   ahr[mt], whr[p][0], whr[p][2]);
                    mma_f16(acc[mt][2*p+1], ahr[mt], whr[p][1], whr[p][3]);
                }
        }

        if (kt+2 < 32){
            int st2 = (kt+2) - ((kt+2)/3)*3;
            load_stage(st2, kt+2);
        }
        asm volatile("cp.async.commit_group;");
        __syncthreads();
    }

    const int row0 = m0 + warp_m + (lane>>2);
    const int col0 = n0 + warp_n + ((lane&3)<<1);
    #pragma unroll
    for (int mt=0; mt<4; mt++){
        #pragma unroll
        for (int nt=0; nt<4; nt++){
            float* p0 = C + (size_t)(row0 + mt*16)*Dn + col0 + nt*8;
            float* p1 = p0 + 8*(size_t)Dn;
            *(float2*)p0 = make_float2(acc[mt][nt][0], acc[mt][nt][1]);
            *(float2*)p1 = make_float2(acc[mt][nt][2], acc[mt][nt][3]);
        }
    }
}

// ======================= fp16 tensor-core flash attention ===================
// Q pre-scaled (log2 units). KB=128, 2-stage, two-barrier pipeline. (R13 exact)
#define QLD 6144
#define AT_ROWB 272
#define AT_K    0
#define AT_V    34816
#define AT_STAGE 69632
#define AT_QOFF (2*AT_STAGE)
#define AT_SMEM (2*AT_STAGE + 34816)         // 174080

__global__ __launch_bounds__(256, 1)
void attn_mma(const __half* __restrict__ QKV, __half* __restrict__ OgH)
{
    extern __shared__ char sm[];
    uint32_t sb = smem_u32(sm);
    const int tid = threadIdx.x, w = tid>>5, lane = tid&31;
    const int qb = (int)(gridDim.x - 1 - blockIdx.x);
    const int bh = blockIdx.y;
    const int b = bh>>4, h = bh&15;
    const size_t rowbase = (size_t)b*Ln;
    const size_t colb = (size_t)h*128;

    {
        #pragma unroll
        for (int j=0;j<8;j++){
            int c = tid + j*256;
            int r = c>>4, seg = c&15;
            const char* src = (const char*)QKV
                + (((rowbase + (size_t)qb*128 + r)*QLD + colb)<<1) + seg*16;
            cp16(sb + AT_QOFF + r*AT_ROWB + seg*16, src);
        }
        asm volatile("cp.async.commit_group;");
    }
    auto issue_kv = [&](int kb2, int st){
        uint32_t sbase = sb + st*AT_STAGE;
        #pragma unroll
        for (int j=0;j<16;j++){
            int c = tid + j*256;
            int arr = c>>11, r = (c>>4)&127, seg = c&15;
            size_t coff = colb + (size_t)((1+arr)*Dn);
            const char* src = (const char*)QKV
                + (((rowbase + (size_t)kb2*128 + r)*QLD + coff)<<1) + seg*16;
            cp16(sbase + arr*AT_V + r*AT_ROWB + seg*16, src);
        }
    };
    issue_kv(0, 0);
    asm volatile("cp.async.commit_group;");

    asm volatile("cp.async.wait_group 1;");
    __syncthreads();
    uint32_t qf[8][4];
    {
        uint32_t qa = sb + AT_QOFF + (uint32_t)(w*16 + (lane&15))*AT_ROWB + ((lane>>4)<<4);
        #pragma unroll
        for (int ks=0; ks<8; ks++) ldsm4(qf[ks], qa + ks*32);
    }

    float o[16][4];
    #pragma unroll
    for (int i=0;i<16;i++){ o[i][0]=0.f;o[i][1]=0.f;o[i][2]=0.f;o[i][3]=0.f; }
    float m0 = -1e30f, m1 = -1e30f, l0 = 0.f, l1 = 0.f;
    const int grow0 = qb*128 + w*16 + (lane>>2);

    for (int kb=0; kb<=qb; ++kb){
        __syncthreads();
        if (kb+1 <= qb) issue_kv(kb+1, (kb+1)&1);
        asm volatile("cp.async.commit_group;");
        asm volatile("cp.async.wait_group 1;");
        __syncthreads();
        uint32_t base = sb + (uint32_t)(kb&1)*AT_STAGE;

        // ---- S = Q K^T (Q pre-scaled) ----
        float s[16][4];
        #pragma unroll
        for (int j=0;j<16;j++){ s[j][0]=0.f;s[j][1]=0.f;s[j][2]=0.f;s[j][3]=0.f; }
        uint32_t kaBase = base + AT_K + (uint32_t)(lane&15)*AT_ROWB + ((lane>>4)<<4);
        #pragma unroll
        for (int ks=0; ks<8; ks++){
            #pragma unroll
            for (int p2=0; p2<8; p2++){
                uint32_t kf[4];
                ldsm4(kf, kaBase + (uint32_t)p2*(16*AT_ROWB) + ks*32);
                mma_f16(s[2*p2],   qf[ks], kf[0], kf[2]);
                mma_f16(s[2*p2+1], qf[ks], kf[1], kf[3]);
            }
        }

        // ---- causal mask only (scale folded into Q) ----
        if (kb == qb){
            #pragma unroll
            for (int j=0;j<16;j++){
                int gc = kb*128 + j*8 + ((lane&3)<<1);
                if (gc   > grow0)   s[j][0] = -1e30f;
                if (gc+1 > grow0)   s[j][1] = -1e30f;
                if (gc   > grow0+8) s[j][2] = -1e30f;
                if (gc+1 > grow0+8) s[j][3] = -1e30f;
            }
        }

        // ---- base-2 online softmax ----
        float rm0 = -1e30f, rm1 = -1e30f;
        #pragma unroll
        for (int j=0;j<16;j++){
            rm0 = fmaxf(rm0, fmaxf(s[j][0], s[j][1]));
            rm1 = fmaxf(rm1, fmaxf(s[j][2], s[j][3]));
        }
        rm0 = fmaxf(rm0, __shfl_xor_sync(0xffffffffu, rm0, 1));
        rm0 = fmaxf(rm0, __shfl_xor_sync(0xffffffffu, rm0, 2));
        rm1 = fmaxf(rm1, __shfl_xor_sync(0xffffffffu, rm1, 1));
        rm1 = fmaxf(rm1, __shfl_xor_sync(0xffffffffu, rm1, 2));
        float mN0 = fmaxf(m0, rm0), mN1 = fmaxf(m1, rm1);
        float fac0 = ex2(m0 - mN0), fac1 = ex2(m1 - mN1);
        m0 = mN0; m1 = mN1;
        float rs0 = 0.f, rs1 = 0.f;
        #pragma unroll
        for (int j=0;j<16;j++){
            s[j][0] = ex2(s[j][0] - mN0);
            s[j][1] = ex2(s[j][1] - mN0);
            s[j][2] = ex2(s[j][2] - mN1);
            s[j][3] = ex2(s[j][3] - mN1);
            rs0 += s[j][0] + s[j][1];
            rs1 += s[j][2] + s[j][3];
        }
        rs0 += __shfl_xor_sync(0xffffffffu, rs0, 1);
        rs0 += __shfl_xor_sync(0xffffffffu, rs0, 2);
        rs1 += __shfl_xor_sync(0xffffffffu, rs1, 1);
        rs1 += __shfl_xor_sync(0xffffffffu, rs1, 2);
        l0 = l0*fac0 + rs0;
        l1 = l1*fac1 + rs1;
        #pragma unroll
        for (int i=0;i<16;i++){
            o[i][0]*=fac0; o[i][1]*=fac0; o[i][2]*=fac1; o[i][3]*=fac1;
        }

        // ---- O += P V ----
        uint32_t vaBase = base + AT_V
            + ((uint32_t)(lane&7) + (((lane>>3)&1)<<3))*AT_ROWB
            + (((lane>>4)<<3)<<1);
        #pragma unroll
        for (int ks=0; ks<8; ks++){
            uint32_t aP[4];
            aP[0] = packh2(s[2*ks][0],   s[2*ks][1]);
            aP[1] = packh2(s[2*ks][2],   s[2*ks][3]);
            aP[2] = packh2(s[2*ks+1][0], s[2*ks+1][1]);
            aP[3] = packh2(s[2*ks+1][2], s[2*ks+1][3]);
            #pragma unroll
            for (int nt2=0; nt2<8; nt2++){
                uint32_t vf[4];
                ldsm4t(vf, vaBase + (uint32_t)ks*(16*AT_ROWB) + (uint32_t)nt2*32);
                mma_f16(o[2*nt2],   aP, vf[0], vf[1]);
                mma_f16(o[2*nt2+1], aP, vf[2], vf[3]);
            }
        }
    }

    float inv0 = 1.0f/l0, inv1 = 1.0f/l1;
    size_t r0off = (rowbase + (size_t)grow0)*Dn + colb + ((lane&3)<<1);
    size_t r1off = r0off + 8*(size_t)Dn;
    #pragma unroll
    for (int nt=0; nt<16; nt++){
        *(uint32_t*)&OgH[r0off + nt*8] = packh2(o[nt][0]*inv0, o[nt][1]*inv0);
        *(uint32_t*)&OgH[r1off + nt*8] = packh2(o[nt][2]*inv1, o[nt][3]*inv1);
    }
}

// ======================= launch =============================================
extern "C" void kernel_launch(void* const* d_in, const int* in_sizes, int n_in,
                              void* d_out, int out_size) {
    const float* x  = (const float*)d_in[0];
    const int*   tp = (const int*)d_in[2];
    const float* Wq = (const float*)d_in[3];
    const float* Wk = (const float*)d_in[4];
    const float* Wv = (const float*)d_in[5];
    const float* Wo = (const float*)d_in[6];
    float* out = (float*)d_out;

    __half *xH, *wH, *OH, *QKVf;
    cudaGetSymbolAddress((void**)&xH, g_xH);
    cudaGetSymbolAddress((void**)&wH, g_wH);
    cudaGetSymbolAddress((void**)&OH, g_OH);
    cudaGetSymbolAddress((void**)&QKVf, g_QKVf);
    const size_t WS = (size_t)Dn*Dn;

    cudaFuncSetAttribute((const void*)gemm_qkv,
                         cudaFuncAttributeMaxDynamicSharedMemorySize, QG_SMEM);
    cudaFuncSetAttribute((const void*)gemm_fp16,
                         cudaFuncAttributeMaxDynamicSharedMemorySize, FG_SMEM);
    cudaFuncSetAttribute((const void*)attn_mma,
                         cudaFuncAttributeMaxDynamicSharedMemorySize, AT_SMEM);

    // fp16 conversion of x + weights, and rope tables, one launch
    conv_all<<<dim3((Dn*Dn/4 + 255)/256, 7), 256>>>(x, Wq, Wk, Wv, Wo);

    // fused QKV projection + RoPE(+scale) + fp16  (128x192, BK=64)
    gemm_qkv<<<dim3(NQKV/192, MROWS/128), 256, QG_SMEM>>>(xH, wH, tp, QKVf);

    // flash attention (fp16 MMA, KB=128, two-barrier pipeline, f32 ex2)
    attn_mma<<<dim3(Ln/128, Bn*Hn), 256, AT_SMEM>>>(QKVf, OH);

    // output projection (128x128, BK=64, occ2)
    gemm_fp16<<<dim3(Dn/128, MROWS/128), 256, FG_SMEM>>>(OH, wH+3*WS, out);
}

// round 16
// speedup vs baseline: 1.0614x; 1.0614x over previous
#include <cuda_runtime.h>
#include <cuda_fp16.h>
#include <math.h>
#include <stdint.h>

#define Bn 2
#define Ln 2048
#define Dn 2048
#define Hn 16
#define DHn 128
#define MROWS (Bn*Ln)          // 4096
#define NQKV  (3*Dn)           // 6144
#define MAXPOS 4096

// ---------------- scratch (device globals; no allocation allowed) ----------
__device__ __half g_xH[(size_t)MROWS*Dn];
__device__ __half g_wH[4][(size_t)Dn*Dn];      // Wq,Wk,Wv contiguous; Wo last
__device__ __half g_QKVf[(size_t)MROWS*NQKV];  // fused Q|K|V fp16, post-RoPE (Q pre-scaled)
__device__ __half g_OH[(size_t)MROWS*Dn];
__device__ float g_cos[MAXPOS*64];
__device__ float g_sin[MAXPOS*64];

// ======================= helpers ============================================
__device__ __forceinline__ uint32_t smem_u32(const void* p){
    uint32_t a;
    asm("{ .reg .u64 t; cvta.to.shared.u64 t, %1; cvt.u32.u64 %0, t; }" : "=r"(a) : "l"(p));
    return a;
}
__device__ __forceinline__ void cp16(uint32_t s, const void* g){
    asm volatile("cp.async.cg.shared.global [%0], [%1], 16;" :: "r"(s), "l"(g));
}
__device__ __forceinline__ void ldsm4(uint32_t* r, uint32_t a){
    asm volatile("ldmatrix.sync.aligned.m8n8.x4.shared.b16 {%0,%1,%2,%3},[%4];"
        : "=r"(r[0]),"=r"(r[1]),"=r"(r[2]),"=r"(r[3]) : "r"(a));
}
__device__ __forceinline__ void ldsm4t(uint32_t* r, uint32_t a){
    asm volatile("ldmatrix.sync.aligned.m8n8.x4.trans.shared.b16 {%0,%1,%2,%3},[%4];"
        : "=r"(r[0]),"=r"(r[1]),"=r"(r[2]),"=r"(r[3]) : "r"(a));
}
__device__ __forceinline__ void mma_f16(float* c, const uint32_t* a, uint32_t b0, uint32_t b1){
    asm volatile("mma.sync.aligned.m16n8k16.row.col.f32.f16.f16.f32 "
        "{%0,%1,%2,%3},{%4,%5,%6,%7},{%8,%9},{%0,%1,%2,%3};"
        : "+f"(c[0]),"+f"(c[1]),"+f"(c[2]),"+f"(c[3])
        : "r"(a[0]),"r"(a[1]),"r"(a[2]),"r"(a[3]),"r"(b0),"r"(b1));
}
__device__ __forceinline__ uint32_t packh2(float x, float y){
    __half2 h = __floats2half2_rn(x, y);
    return *(uint32_t*)&h;
}
__device__ __forceinline__ float ex2(float x){
    float r;
    asm("ex2.approx.f32 %0, %1;" : "=f"(r) : "f"(x));
    return r;
}

// ======================= conversion + RoPE tables (1 launch) ================
// grid (1024, 7). y 0..3 -> weights, 4..5 -> x halves, 6 -> rope tables.
// Conversion branches: 4 x float4 per thread (MLP=4), coalesced per step.
__global__ void conv_all(const float* __restrict__ x,
                         const float* __restrict__ Wq, const float* __restrict__ Wk,
                         const float* __restrict__ Wv, const float* __restrict__ Wo)
{
    const int n4w = Dn*Dn/4;           // 1048576 float4 per array
    int y = blockIdx.y;
    if (y == 6){
        int idx = blockIdx.x*blockDim.x + threadIdx.x;
        if (idx >= MAXPOS*64) return;
        int pos = idx >> 6;
        int i   = idx & 63;
        float expo = (float)(2*i) * (1.0f/128.0f);
        float inv  = 1.0f / powf(10000.0f, expo);
        float ang  = (float)pos * inv;
        g_cos[idx] = cosf(ang);
        g_sin[idx] = sinf(ang);
        return;
    }
    const float* src;
    __half* dst;
    if (y < 4){
        src = (y==0)?Wq:((y==1)?Wk:((y==2)?Wv:Wo));
        dst = &g_wH[y][0];
    } else {
        src = x  + (size_t)(y-4)*n4w*4;
        dst = g_xH + (size_t)(y-4)*n4w*4;
    }
    int base = blockIdx.x*1024 + threadIdx.x;   // 1024 blocks cover n4w exactly
    float4 v[4];
    #pragma unroll
    for (int k=0;k<4;k++) v[k] = ((const float4*)src)[base + k*256];
    #pragma unroll
    for (int k=0;k<4;k++)
        ((uint2*)dst)[base + k*256] = make_uint2(packh2(v[k].x,v[k].y), packh2(v[k].z,v[k].w));
}

// ======================= fused QKV GEMM + RoPE epilogue =====================
// Tile 128x192, 8 warps (2x4), warp tile 64x48, BK=32, 3-stage, OCC=1. (R13)
#define QSW     10240
#define QSTAGE  25600
#define QG_SMEM (3*QSTAGE)            // 76800

__global__ __launch_bounds__(256)
void gemm_qkv(const __half* __restrict__ A, const __half* __restrict__ W,
              const int* __restrict__ tp, __half* __restrict__ Cf)
{
    extern __shared__ char smem[];
    uint32_t sb = smem_u32(smem);
    const int tid = threadIdx.x, wid = tid>>5, lane = tid&31;
    const int m0 = blockIdx.y*128, n0 = blockIdx.x*192;
    const int warp_m = (wid>>2)*64, warp_n = (wid&3)*48;

    auto load_stage = [&](int st, int kt){
        uint32_t sbase = sb + st*QSTAGE;
        #pragma unroll
        for (int j=0;j<5;j++){
            int c = tid + j*256;
            if (c < 512){
                int row = c>>2, seg = c&3;
                cp16(sbase + row*80 + seg*16,
                     A + (size_t)(m0+row)*Dn + kt*32 + seg*8);
            } else {
                int cc = c - 512; int row = cc>>2, seg = cc&3;
                cp16(sbase + QSW + row*80 + seg*16,
                     W + (size_t)(n0+row)*Dn + kt*32 + seg*8);
            }
        }
    };

    float acc[4][6][4];
    #pragma unroll
    for (int i=0;i<4;i++)
        #pragma unroll
        for (int j=0;j<6;j++)
            #pragma unroll
            for (int q=0;q<4;q++) acc[i][j][q]=0.f;

    load_stage(0, 0);
    asm volatile("cp.async.commit_group;");
    load_stage(1, 1);
    asm volatile("cp.async.commit_group;");

    const int lrow = lane & 15;
    const uint32_t lcolB = (uint32_t)((lane>>4)<<4);

    for (int kt=0; kt<64; ++kt){
        int st = kt - (kt/3)*3;
        uint32_t base = sb + st*QSTAGE;
        asm volatile("cp.async.wait_group 1;");
        __syncthreads();

        #pragma unroll
        for (int ks=0; ks<2; ++ks){
            uint32_t kB = ks*32;
            uint32_t aAddr = base + (uint32_t)(warp_m + lrow)*80 + lcolB + kB;
            uint32_t wAddr = base + QSW + (uint32_t)(warp_n + lrow)*80 + lcolB + kB;

            uint32_t ahr[4][4], whr[3][4];
            #pragma unroll
            for (int mt=0; mt<4; mt++) ldsm4(ahr[mt], aAddr + mt*(16*80));
            #pragma unroll
            for (int p=0; p<3; p++)   ldsm4(whr[p], wAddr + p*(16*80));
            #pragma unroll
            for (int mt=0; mt<4; mt++)
                #pragma unroll
                for (int p=0; p<3; p++){
                    mma_f16(acc[mt][2*p],   ahr[mt], whr[p][0], whr[p][2]);
                    mma_f16(acc[mt][2*p+1], ahr[mt], whr[p][1], whr[p][3]);
                }
        }

        if (kt+2 < 64){
            int st2 = (kt+2) - ((kt+2)/3)*3;
            load_stage(st2, kt+2);
        }
        asm volatile("cp.async.commit_group;");
        __syncthreads();
    }

    // ---- epilogue: RoPE (Q: * scale2, K: plain) + fp16 store ----
    const float scale2 = 0.12753785166876984f;   // 1/sqrt(128)*log2(e)
    const int row0 = m0 + warp_m + (lane>>2);
    const int col0 = n0 + warp_n + ((lane&3)<<1);
    int pos[8];
    #pragma unroll
    for (int mt=0; mt<4; mt++){
        pos[2*mt]   = tp[row0 + mt*16];
        pos[2*mt+1] = tp[row0 + mt*16 + 8];
    }
    #pragma unroll
    for (int nt=0; nt<6; nt++){
        int col = col0 + nt*8;
        bool dorope = (col < 2*Dn);
        float qs = (col < Dn) ? scale2 : 1.0f;
        int ii = (col & 127) >> 1;
        #pragma unroll
        for (int mt=0; mt<4; mt++){
            float a0=acc[mt][nt][0], a1=acc[mt][nt][1];
            float a2=acc[mt][nt][2], a3=acc[mt][nt][3];
            uint32_t o0, o1;
            if (dorope){
                int p0 = pos[2*mt]*64 + ii, p1 = pos[2*mt+1]*64 + ii;
                float c0=g_cos[p0]*qs, s0=g_sin[p0]*qs;
                float c1=g_cos[p1]*qs, s1=g_sin[p1]*qs;
                o0 = packh2(a0*c0 - a1*s0, a0*s0 + a1*c0);
                o1 = packh2(a2*c1 - a3*s1, a2*s1 + a3*c1);
            } else {
                o0 = packh2(a0, a1);
                o1 = packh2(a2, a3);
            }
            *(uint32_t*)&Cf[(size_t)(row0 + mt*16)*NQKV + col]     = o0;
            *(uint32_t*)&Cf[(size_t)(row0 + mt*16 + 8)*NQKV + col] = o1;
        }
    }
}

// ======================= fp16 GEMM (output projection) ======================
// 128x128 tile, warp 64x32, BK=64, 3-stage, OCC=2.  (R12/R13 measured win)
#define FAW     18432
#define FSTAGE  36864
#define FG_SMEM (3*FSTAGE)            // 110592

__global__ __launch_bounds__(256, 2)
void gemm_fp16(const __half* __restrict__ A, const __half* __restrict__ W,
               float* __restrict__ C)
{
    extern __shared__ char smem[];
    uint32_t sb = smem_u32(smem);
    const int tid = threadIdx.x, wid = tid>>5, lane = tid&31;
    const int m0 = blockIdx.y*128, n0 = blockIdx.x*128;
    const int warp_m = (wid>>2)*64, warp_n = (wid&3)*32;

    auto load_stage = [&](int st, int kt){
        uint32_t sbase = sb + st*FSTAGE;
        #pragma unroll
        for (int j=0;j<8;j++){
            int c = tid + j*256;
            if (c < 1024){
                int row = c>>3, seg = c&7;
                cp16(sbase + row*144 + seg*16,
                     A + (size_t)(m0+row)*Dn + kt*64 + seg*8);
            } else {
                int cc = c - 1024; int row = cc>>3, seg = cc&7;
                cp16(sbase + FAW + row*144 + seg*16,
                     W + (size_t)(n0+row)*Dn + kt*64 + seg*8);
            }
        }
    };

    float acc[4][4][4];
    #pragma unroll
    for (int i=0;i<4;i++)
        #pragma unroll
        for (int j=0;j<4;j++)
            #pragma unroll
            for (int q=0;q<4;q++) acc[i][j][q]=0.f;

    load_stage(0, 0);
    asm volatile("cp.async.commit_group;");
    load_stage(1, 1);
    asm volatile("cp.async.commit_group;");

    const int lrow = lane & 15;
    const uint32_t lcolB = (uint32_t)((lane>>4)<<4);

    for (int kt=0; kt<32; ++kt){
        int st = kt - (kt/3)*3;
        uint32_t base = sb + st*FSTAGE;
        asm volatile("cp.async.wait_group 1;");
        __syncthreads();

        #pragma unroll
        for (int ks=0; ks<4; ++ks){
            uint32_t kB = ks*32;
            uint32_t aAddr = base + (uint32_t)(warp_m + lrow)*144 + lcolB + kB;
            uint32_t wAddr = base + FAW + (uint32_t)(warp_n + lrow)*144 + lcolB + kB;

            uint32_t ahr[4][4], whr[2][4];
            #pragma unroll
            for (int mt=0; mt<4; mt++) ldsm4(ahr[mt], aAddr + mt*(16*144));
            #pragma unroll
            for (int p=0; p<2; p++)   ldsm4(whr[p], wAddr + p*(16*144));
            #pragma unroll
            for (int mt=0; mt<4; mt++)
                #pragma unroll
                for (int p=0; p<2; p++){
                    mma_f16(acc[mt][2*p],   ahr[mt], whr[p][0], whr[p][2]);
                    mma_f16(acc[mt][2*p+1], ahr[mt], whr[p][1], whr[p][3]);
                }
        }

        if (kt+2 < 32){
            int st2 = (kt+2) - ((kt+2)/3)*3;
            load_stage(st2, kt+2);
        }
        asm volatile("cp.async.commit_group;");
        __syncthreads();
    }

    const int row0 = m0 + warp_m + (lane>>2);
    const int col0 = n0 + warp_n + ((lane&3)<<1);
    #pragma unroll
    for (int mt=0; mt<4; mt++){
        #pragma unroll
        for (int nt=0; nt<4; nt++){
            float* p0 = C + (size_t)(row0 + mt*16)*Dn + col0 + nt*8;
            float* p1 = p0 + 8*(size_t)Dn;
            *(float2*)p0 = make_float2(acc[mt][nt][0], acc[mt][nt][1]);
            *(float2*)p1 = make_float2(acc[mt][nt][2], acc[mt][nt][3]);
        }
    }
}

// ======================= fp16 tensor-core flash attention ===================
// Q pre-scaled (log2 units). KB=128, 2-stage, two-barrier pipeline. (R13 exact)
#define QLD 6144
#define AT_ROWB 272
#define AT_K    0
#define AT_V    34816
#define AT_STAGE 69632
#define AT_QOFF (2*AT_STAGE)
#define AT_SMEM (2*AT_STAGE + 34816)         // 174080

__global__ __launch_bounds__(256, 1)
void attn_mma(const __half* __restrict__ QKV, __half* __restrict__ OgH)
{
    extern __shared__ char sm[];
    uint32_t sb = smem_u32(sm);
    const int tid = threadIdx.x, w = tid>>5, lane = tid&31;
    const int qb = (int)(gridDim.x - 1 - blockIdx.x);
    const int bh = blockIdx.y;
    const int b = bh>>4, h = bh&15;
    const size_t rowbase = (size_t)b*Ln;
    const size_t colb = (size_t)h*128;

    {
        #pragma unroll
        for (int j=0;j<8;j++){
            int c = tid + j*256;
            int r = c>>4, seg = c&15;
            const char* src = (const char*)QKV
                + (((rowbase + (size_t)qb*128 + r)*QLD + colb)<<1) + seg*16;
            cp16(sb + AT_QOFF + r*AT_ROWB + seg*16, src);
        }
        asm volatile("cp.async.commit_group;");
    }
    auto issue_kv = [&](int kb2, int st){
        uint32_t sbase = sb + st*AT_STAGE;
        #pragma unroll
        for (int j=0;j<16;j++){
            int c = tid + j*256;
            int arr = c>>11, r = (c>>4)&127, seg = c&15;
            size_t coff = colb + (size_t)((1+arr)*Dn);
            const char* src = (const char*)QKV
                + (((rowbase + (size_t)kb2*128 + r)*QLD + coff)<<1) + seg*16;
            cp16(sbase + arr*AT_V + r*AT_ROWB + seg*16, src);
        }
    };
    issue_kv(0, 0);
    asm volatile("cp.async.commit_group;");

    asm volatile("cp.async.wait_group 1;");
    __syncthreads();
    uint32_t qf[8][4];
    {
        uint32_t qa = sb + AT_QOFF + (uint32_t)(w*16 + (lane&15))*AT_ROWB + ((lane>>4)<<4);
        #pragma unroll
        for (int ks=0; ks<8; ks++) ldsm4(qf[ks], qa + ks*32);
    }

    float o[16][4];
    #pragma unroll
    for (int i=0;i<16;i++){ o[i][0]=0.f;o[i][1]=0.f;o[i][2]=0.f;o[i][3]=0.f; }
    float m0 = -1e30f, m1 = -1e30f, l0 = 0.f, l1 = 0.f;
    const int grow0 = qb*128 + w*16 + (lane>>2);

    for (int kb=0; kb<=qb; ++kb){
        __syncthreads();
        if (kb+1 <= qb) issue_kv(kb+1, (kb+1)&1);
        asm volatile("cp.async.commit_group;");
        asm volatile("cp.async.wait_group 1;");
        __syncthreads();
        uint32_t base = sb + (uint32_t)(kb&1)*AT_STAGE;

        // ---- S = Q K^T (Q pre-scaled) ----
        float s[16][4];
        #pragma unroll
        for (int j=0;j<16;j++){ s[j][0]=0.f;s[j][1]=0.f;s[j][2]=0.f;s[j][3]=0.f; }
        uint32_t kaBase = base + AT_K + (uint32_t)(lane&15)*AT_ROWB + ((lane>>4)<<4);
        #pragma unroll
        for (int ks=0; ks<8; ks++){
            #pragma unroll
            for (int p2=0; p2<8; p2++){
                uint32_t kf[4];
                ldsm4(kf, kaBase + (uint32_t)p2*(16*AT_ROWB) + ks*32);
                mma_f16(s[2*p2],   qf[ks], kf[0], kf[2]);
                mma_f16(s[2*p2+1], qf[ks], kf[1], kf[3]);
            }
        }

        // ---- causal mask only (scale folded into Q) ----
        if (kb == qb){
            #pragma unroll
            for (int j=0;j<16;j++){
                int gc = kb*128 + j*8 + ((lane&3)<<1);
                if (gc   > grow0)   s[j][0] = -1e30f;
                if (gc+1 > grow0)   s[j][1] = -1e30f;
                if (gc   > grow0+8) s[j][2] = -1e30f;
                if (gc+1 > grow0+8) s[j][3] = -1e30f;
            }
        }

        // ---- base-2 online softmax ----
        float rm0 = -1e30f, rm1 = -1e30f;
        #pragma unroll
        for (int j=0;j<16;j++){
            rm0 = fmaxf(rm0, fmaxf(s[j][0], s[j][1]));
            rm1 = fmaxf(rm1, fmaxf(s[j][2], s[j][3]));
        }
        rm0 = fmaxf(rm0, __shfl_xor_sync(0xffffffffu, rm0, 1));
        rm0 = fmaxf(rm0, __shfl_xor_sync(0xffffffffu, rm0, 2));
        rm1 = fmaxf(rm1, __shfl_xor_sync(0xffffffffu, rm1, 1));
        rm1 = fmaxf(rm1, __shfl_xor_sync(0xffffffffu, rm1, 2));
        float mN0 = fmaxf(m0, rm0), mN1 = fmaxf(m1, rm1);
        float fac0 = ex2(m0 - mN0), fac1 = ex2(m1 - mN1);
        m0 = mN0; m1 = mN1;
        float rs0 = 0.f, rs1 = 0.f;
        #pragma unroll
        for (int j=0;j<16;j++){
            s[j][0] = ex2(s[j][0] - mN0);
            s[j][1] = ex2(s[j][1] - mN0);
            s[j][2] = ex2(s[j][2] - mN1);
            s[j][3] = ex2(s[j][3] - mN1);
            rs0 += s[j][0] + s[j][1];
            rs1 += s[j][2] + s[j][3];
        }
        rs0 += __shfl_xor_sync(0xffffffffu, rs0, 1);
        rs0 += __shfl_xor_sync(0xffffffffu, rs0, 2);
        rs1 += __shfl_xor_sync(0xffffffffu, rs1, 1);
        rs1 += __shfl_xor_sync(0xffffffffu, rs1, 2);
        l0 = l0*fac0 + rs0;
        l1 = l1*fac1 + rs1;
        #pragma unroll
        for (int i=0;i<16;i++){
            o[i][0]*=fac0; o[i][1]*=fac0; o[i][2]*=fac1; o[i][3]*=fac1;
        }

        // ---- O += P V ----
        uint32_t vaBase = base + AT_V
            + ((uint32_t)(lane&7) + (((lane>>3)&1)<<3))*AT_ROWB
            + (((lane>>4)<<3)<<1);
        #pragma unroll
        for (int ks=0; ks<8; ks++){
            uint32_t aP[4];
            aP[0] = packh2(s[2*ks][0],   s[2*ks][1]);
            aP[1] = packh2(s[2*ks][2],   s[2*ks][3]);
            aP[2] = packh2(s[2*ks+1][0], s[2*ks+1][1]);
            aP[3] = packh2(s[2*ks+1][2], s[2*ks+1][3]);
            #pragma unroll
            for (int nt2=0; nt2<8; nt2++){
                uint32_t vf[4];
                ldsm4t(vf, vaBase + (uint32_t)ks*(16*AT_ROWB) + (uint32_t)nt2*32);
                mma_f16(o[2*nt2],   aP, vf[0], vf[1]);
                mma_f16(o[2*nt2+1], aP, vf[2], vf[3]);
            }
        }
    }

    float inv0 = 1.0f/l0, inv1 = 1.0f/l1;
    size_t r0off = (rowbase + (size_t)grow0)*Dn + colb + ((lane&3)<<1);
    size_t r1off = r0off + 8*(size_t)Dn;
    #pragma unroll
    for (int nt=0; nt<16; nt++){
        *(uint32_t*)&OgH[r0off + nt*8] = packh2(o[nt][0]*inv0, o[nt][1]*inv0);
        *(uint32_t*)&OgH[r1off + nt*8] = packh2(o[nt][2]*inv1, o[nt][3]*inv1);
    }
}

// ======================= launch =============================================
extern "C" void kernel_launch(void* const* d_in, const int* in_sizes, int n_in,
                              void* d_out, int out_size) {
    const float* x  = (const float*)d_in[0];
    const int*   tp = (const int*)d_in[2];
    const float* Wq = (const float*)d_in[3];
    const float* Wk = (const float*)d_in[4];
    const float* Wv = (const float*)d_in[5];
    const float* Wo = (const float*)d_in[6];
    float* out = (float*)d_out;

    __half *xH, *wH, *OH, *QKVf;
    cudaGetSymbolAddress((void**)&xH, g_xH);
    cudaGetSymbolAddress((void**)&wH, g_wH);
    cudaGetSymbolAddress((void**)&OH, g_OH);
    cudaGetSymbolAddress((void**)&QKVf, g_QKVf);
    const size_t WS = (size_t)Dn*Dn;

    cudaFuncSetAttribute((const void*)gemm_qkv,
                         cudaFuncAttributeMaxDynamicSharedMemorySize, QG_SMEM);
    cudaFuncSetAttribute((const void*)gemm_fp16,
                         cudaFuncAttributeMaxDynamicSharedMemorySize, FG_SMEM);
    cudaFuncSetAttribute((const void*)attn_mma,
                         cudaFuncAttributeMaxDynamicSharedMemorySize, AT_SMEM);

    // fp16 conversion of x + weights (4x float4/thread), rope tables — 1 launch
    conv_all<<<dim3(1024, 7), 256>>>(x, Wq, Wk, Wv, Wo);

    // fused QKV projection + RoPE(+scale) + fp16  (128x192, BK=32, R13 config)
    gemm_qkv<<<dim3(NQKV/192, MROWS/128), 256, QG_SMEM>>>(xH, wH, tp, QKVf);

    // flash attention (fp16 MMA, KB=128, two-barrier pipeline, f32 ex2)
    attn_mma<<<dim3(Ln/128, Bn*Hn), 256, AT_SMEM>>>(QKVf, OH);

    // output projection (128x128, BK=64, occ2)
    gemm_fp16<<<dim3(Dn/128, MROWS/128), 256, FG_SMEM>>>(OH, wH+3*WS, out);
}